// round 1
// baseline (speedup 1.0000x reference)
#include <cuda_runtime.h>
#include <cuda_bf16.h>
#include <math.h>

#define NN 50000
#define EE 800000
#define GG 512
#define LN_EPS 1e-5f
#define NEG_SLOPE 0.2f

// ---------------- device scratch (static globals; no runtime allocation) ----
__device__ float g_xl[NN * 256];
__device__ float g_xr[NN * 256];
__device__ float g_h[NN * 256];
__device__ float g_acc[NN * 256];
__device__ float g_logit[EE * 4];
__device__ int   g_rowptr[NN + 1];
__device__ int   g_cnt[NN];
__device__ int   g_eidx[EE];
__device__ float g_red[2];
__device__ float g_pool[GG * 64];
__device__ float g_pcnt[GG];

__device__ __forceinline__ float lrelu(float v) {
    return v > 0.f ? v : NEG_SLOPE * v;
}

// ---------------- CSR build --------------------------------------------------
__global__ void k_zero_cnt() {
    int i = blockIdx.x * blockDim.x + threadIdx.x;
    if (i < NN) g_cnt[i] = 0;
}

__global__ void k_hist(const int* __restrict__ dst) {
    int e = blockIdx.x * blockDim.x + threadIdx.x;
    if (e < EE) atomicAdd(&g_cnt[dst[e]], 1);
}

// single-block chunked inclusive scan -> rowptr, and exclusive -> cursor (g_cnt)
__global__ void k_scan() {
    __shared__ int sh[1024];
    __shared__ int s_carry;
    int tid = threadIdx.x;
    if (tid == 0) { s_carry = 0; g_rowptr[0] = 0; }
    __syncthreads();
    for (int base = 0; base < NN; base += 1024) {
        int i = base + tid;
        int v = (i < NN) ? g_cnt[i] : 0;
        sh[tid] = v;
        __syncthreads();
        #pragma unroll
        for (int off = 1; off < 1024; off <<= 1) {
            int t = (tid >= off) ? sh[tid - off] : 0;
            __syncthreads();
            sh[tid] += t;
            __syncthreads();
        }
        int inc = sh[tid];
        int carry = s_carry;
        if (i < NN) {
            g_rowptr[i + 1] = carry + inc;
            g_cnt[i] = carry + inc - v;   // exclusive prefix = scatter cursor
        }
        __syncthreads();
        if (tid == 1023) s_carry = carry + sh[1023];
        __syncthreads();
    }
}

__global__ void k_scatter(const int* __restrict__ dst) {
    int e = blockIdx.x * blockDim.x + threadIdx.x;
    if (e < EE) {
        int pos = atomicAdd(&g_cnt[dst[e]], 1);
        g_eidx[pos] = e;
    }
}

// ---------------- GEMM: Y[rows,M] = X[rows,K] @ W[K,M] + b -------------------
// 64x64 tile, 256 threads, 4x4 per thread, BK=16
__global__ __launch_bounds__(256) void k_gemm_bias(
    const float* __restrict__ X, const float* __restrict__ W,
    const float* __restrict__ b, float* __restrict__ Y,
    int rows, int K, int M)
{
    __shared__ float As[16][65];
    __shared__ float Bs[16][66];
    int block_row = blockIdx.y * 64;
    int block_col = blockIdx.x * 64;
    int t  = threadIdx.x;
    int tx = t & 15;
    int ty = t >> 4;
    float acc[4][4];
    #pragma unroll
    for (int i = 0; i < 4; i++)
        #pragma unroll
        for (int j = 0; j < 4; j++) acc[i][j] = 0.f;

    for (int k0 = 0; k0 < K; k0 += 16) {
        // load A tile (64 rows x 16 k)
        {
            int kk = t & 15;
            int mm = t >> 4;
            #pragma unroll
            for (int i = 0; i < 4; i++) {
                int m = mm + i * 16;
                int r = block_row + m;
                As[kk][m] = (r < rows) ? X[(size_t)r * K + k0 + kk] : 0.f;
            }
        }
        // load B tile (16 k x 64 n)
        {
            int nn = t & 63;
            int kk = t >> 6;
            #pragma unroll
            for (int i = 0; i < 4; i++) {
                int k = kk + i * 4;
                Bs[k][nn] = W[(size_t)(k0 + k) * M + block_col + nn];
            }
        }
        __syncthreads();
        #pragma unroll
        for (int k = 0; k < 16; k++) {
            float a[4], bb[4];
            #pragma unroll
            for (int i = 0; i < 4; i++) a[i] = As[k][ty * 4 + i];
            #pragma unroll
            for (int j = 0; j < 4; j++) bb[j] = Bs[k][tx * 4 + j];
            #pragma unroll
            for (int i = 0; i < 4; i++)
                #pragma unroll
                for (int j = 0; j < 4; j++)
                    acc[i][j] += a[i] * bb[j];
        }
        __syncthreads();
    }
    #pragma unroll
    for (int i = 0; i < 4; i++) {
        int r = block_row + ty * 4 + i;
        if (r < rows) {
            #pragma unroll
            for (int j = 0; j < 4; j++) {
                int c = block_col + tx * 4 + j;
                Y[(size_t)r * M + c] = acc[i][j] + b[c];
            }
        }
    }
}

// ---------------- fused edge attention: logits + segment softmax + aggregate
// one warp per destination node. DM = H*64. Each lane owns dims (lane, lane+32)
// of every head.
template <int H>
__global__ __launch_bounds__(256) void k_edge_attn(
    const int* __restrict__ srcArr,
    const float* __restrict__ att,
    const float* __restrict__ bias)
{
    const int DM = H * 64;
    int warp = (blockIdx.x * blockDim.x + threadIdx.x) >> 5;
    int lane = threadIdx.x & 31;
    if (warp >= NN) return;
    int dn = warp;

    float xr0[H], xr1[H], at0[H], at1[H];
    #pragma unroll
    for (int h = 0; h < H; h++) {
        xr0[h] = g_xr[(size_t)dn * DM + h * 64 + lane];
        xr1[h] = g_xr[(size_t)dn * DM + h * 64 + lane + 32];
        at0[h] = att[h * 64 + lane];
        at1[h] = att[h * 64 + lane + 32];
    }

    int start = g_rowptr[dn];
    int end   = g_rowptr[dn + 1];

    // pass 1: logits + running max (warp-collective per edge)
    float mx[H];
    #pragma unroll
    for (int h = 0; h < H; h++) mx[h] = -INFINITY;

    for (int j = start; j < end; j++) {
        int e = g_eidx[j];
        int s = srcArr[e];
        const float* xlrow = &g_xl[(size_t)s * DM];
        #pragma unroll
        for (int h = 0; h < H; h++) {
            float a = lrelu(xlrow[h * 64 + lane]      + xr0[h]);
            float b = lrelu(xlrow[h * 64 + lane + 32] + xr1[h]);
            float p = a * at0[h] + b * at1[h];
            #pragma unroll
            for (int off = 16; off > 0; off >>= 1)
                p += __shfl_xor_sync(0xffffffffu, p, off);
            if (lane == 0) g_logit[(size_t)e * H + h] = p;
            mx[h] = fmaxf(mx[h], p);
        }
    }

    // pass 2: exp + denominator (lanes split edges)
    float den[H];
    #pragma unroll
    for (int h = 0; h < H; h++) den[h] = 0.f;
    for (int j = start + lane; j < end; j += 32) {
        int e = g_eidx[j];
        #pragma unroll
        for (int h = 0; h < H; h++) {
            float ex = __expf(g_logit[(size_t)e * H + h] - mx[h]);
            g_logit[(size_t)e * H + h] = ex;
            den[h] += ex;
        }
    }
    #pragma unroll
    for (int h = 0; h < H; h++) {
        #pragma unroll
        for (int off = 16; off > 0; off >>= 1)
            den[h] += __shfl_xor_sync(0xffffffffu, den[h], off);
        den[h] = 1.f / fmaxf(den[h], 1e-38f);
    }

    // pass 3: weighted aggregation
    float acc0[H], acc1[H];
    #pragma unroll
    for (int h = 0; h < H; h++) { acc0[h] = 0.f; acc1[h] = 0.f; }
    for (int j = start; j < end; j++) {
        int e = g_eidx[j];
        int s = srcArr[e];
        const float* xlrow = &g_xl[(size_t)s * DM];
        #pragma unroll
        for (int h = 0; h < H; h++) {
            float alpha = g_logit[(size_t)e * H + h] * den[h];
            acc0[h] += alpha * xlrow[h * 64 + lane];
            acc1[h] += alpha * xlrow[h * 64 + lane + 32];
        }
    }
    #pragma unroll
    for (int h = 0; h < H; h++) {
        g_acc[(size_t)dn * DM + h * 64 + lane]      = acc0[h] + bias[h * 64 + lane];
        g_acc[(size_t)dn * DM + h * 64 + lane + 32] = acc1[h] + bias[h * 64 + lane + 32];
    }
}

// ---------------- graph layernorm (global mean/var over all elements) -------
__global__ void k_zero_red() {
    if (threadIdx.x < 2 && blockIdx.x == 0) g_red[threadIdx.x] = 0.f;
}

__global__ __launch_bounds__(256) void k_ln_reduce(int count) {
    float s = 0.f, s2 = 0.f;
    for (int i = blockIdx.x * blockDim.x + threadIdx.x; i < count;
         i += gridDim.x * blockDim.x) {
        float v = g_acc[i];
        s += v; s2 += v * v;
    }
    #pragma unroll
    for (int off = 16; off > 0; off >>= 1) {
        s  += __shfl_xor_sync(0xffffffffu, s,  off);
        s2 += __shfl_xor_sync(0xffffffffu, s2, off);
    }
    __shared__ float shs[8], shs2[8];
    int w = threadIdx.x >> 5, l = threadIdx.x & 31;
    if (l == 0) { shs[w] = s; shs2[w] = s2; }
    __syncthreads();
    if (threadIdx.x == 0) {
        float a = 0.f, b = 0.f;
        for (int i = 0; i < (int)(blockDim.x >> 5); i++) { a += shs[i]; b += shs2[i]; }
        atomicAdd(&g_red[0], a);
        atomicAdd(&g_red[1], b);
    }
}

__global__ __launch_bounds__(256) void k_ln_apply(
    const float* __restrict__ gamma, const float* __restrict__ beta,
    int count, int DM, float invCount, int residual)
{
    int i = blockIdx.x * blockDim.x + threadIdx.x;
    if (i >= count) return;
    int c = i % DM;
    float mu  = g_red[0] * invCount;
    float var = g_red[1] * invCount - mu * mu;
    float rs  = rsqrtf(var + LN_EPS);
    float v = (g_acc[i] - mu) * rs * gamma[c] + beta[c];
    v = fmaxf(v, 0.f);
    if (residual) v += g_h[i];
    g_h[i] = v;
}

// ---------------- pooling + MLP head -----------------------------------------
__global__ void k_zero_pool() {
    int i = blockIdx.x * blockDim.x + threadIdx.x;
    if (i < GG * 64) g_pool[i] = 0.f;
    if (i < GG) g_pcnt[i] = 0.f;
}

__global__ __launch_bounds__(256) void k_pool(const int* __restrict__ batch) {
    int idx = blockIdx.x * blockDim.x + threadIdx.x;
    if (idx >= NN * 64) return;
    int node = idx >> 6;
    int c = idx & 63;
    int g = batch[node];
    atomicAdd(&g_pool[g * 64 + c], g_h[idx]);
    if (c == 0) atomicAdd(&g_pcnt[g], 1.f);
}

__global__ __launch_bounds__(64) void k_mlp(
    const float* __restrict__ Wh1, const float* __restrict__ bh1,
    const float* __restrict__ Wh2, const float* __restrict__ bh2,
    float* __restrict__ out)
{
    int g = blockIdx.x;
    int j = threadIdx.x;
    __shared__ float z[64];
    __shared__ float red[64];
    float cnt = fmaxf(g_pcnt[g], 1.f);
    z[j] = g_pool[g * 64 + j] / cnt;
    __syncthreads();
    float hv = bh1[j];
    #pragma unroll 8
    for (int k = 0; k < 64; k++) hv += z[k] * Wh1[k * 64 + j];
    hv = fmaxf(hv, 0.f);
    red[j] = hv * Wh2[j];
    __syncthreads();
    for (int off = 32; off > 0; off >>= 1) {
        if (j < off) red[j] += red[j + off];
        __syncthreads();
    }
    if (j == 0) out[g] = red[0] + bh2[0];
}

// ---------------- host orchestration ------------------------------------------
extern "C" void kernel_launch(void* const* d_in, const int* in_sizes, int n_in,
                              void* d_out, int out_size)
{
    const float* x     = (const float*)d_in[0];
    const int*   ei    = (const int*)d_in[1];
    const int*   srcA  = ei;
    const int*   dstA  = ei + EE;
    const int*   batch = (const int*)d_in[2];

    const float* Wl[3];  const float* bl[3];
    const float* Wr[3];  const float* br[3];
    const float* att[3]; const float* bias[3];
    const float* lng[3]; const float* lnb[3];
    for (int l = 0; l < 3; l++) {
        int base = 3 + 8 * l;
        Wl[l]   = (const float*)d_in[base + 0];
        bl[l]   = (const float*)d_in[base + 1];
        Wr[l]   = (const float*)d_in[base + 2];
        br[l]   = (const float*)d_in[base + 3];
        att[l]  = (const float*)d_in[base + 4];
        bias[l] = (const float*)d_in[base + 5];
        lng[l]  = (const float*)d_in[base + 6];
        lnb[l]  = (const float*)d_in[base + 7];
    }
    const float* Wh1 = (const float*)d_in[27];
    const float* bh1 = (const float*)d_in[28];
    const float* Wh2 = (const float*)d_in[29];
    const float* bh2 = (const float*)d_in[30];
    float* out = (float*)d_out;

    float *p_xl, *p_xr, *p_h;
    cudaGetSymbolAddress((void**)&p_xl, g_xl);
    cudaGetSymbolAddress((void**)&p_xr, g_xr);
    cudaGetSymbolAddress((void**)&p_h,  g_h);

    // ---- CSR build (edges fixed per launch, rebuilt deterministically) ----
    k_zero_cnt<<<(NN + 255) / 256, 256>>>();
    k_hist<<<(EE + 255) / 256, 256>>>(dstA);
    k_scan<<<1, 1024>>>();
    k_scatter<<<(EE + 255) / 256, 256>>>(dstA);

    // layer configs: {din, dm(=heads*64), heads, residual}
    const int din_[3]  = {128, 256, 64};
    const int dm_[3]   = {256, 64, 64};
    const int res_[3]  = {0, 0, 1};

    for (int l = 0; l < 3; l++) {
        const float* Xin = (l == 0) ? x : p_h;
        int din = din_[l], dm = dm_[l];
        dim3 ggrid(dm / 64, (NN + 63) / 64);
        k_gemm_bias<<<ggrid, 256>>>(Xin, Wl[l], bl[l], p_xl, NN, din, dm);
        k_gemm_bias<<<ggrid, 256>>>(Xin, Wr[l], br[l], p_xr, NN, din, dm);

        int edge_blocks = (NN * 32 + 255) / 256;
        if (l == 0) k_edge_attn<4><<<edge_blocks, 256>>>(srcA, att[l], bias[l]);
        else        k_edge_attn<1><<<edge_blocks, 256>>>(srcA, att[l], bias[l]);

        int count = NN * dm;
        k_zero_red<<<1, 32>>>();
        int rgrid = (count + 255) / 256;
        if (rgrid > 2048) rgrid = 2048;
        k_ln_reduce<<<rgrid, 256>>>(count);
        k_ln_apply<<<(count + 255) / 256, 256>>>(lng[l], lnb[l], count, dm,
                                                 1.f / (float)count, res_[l]);
    }

    // pooling + MLP head
    k_zero_pool<<<(GG * 64 + 255) / 256, 256>>>();
    k_pool<<<(NN * 64 + 255) / 256, 256>>>(batch);
    k_mlp<<<GG, 64>>>(Wh1, bh1, Wh2, bh2, out);

    (void)in_sizes; (void)n_in; (void)out_size;
}

// round 2
// speedup vs baseline: 1.2351x; 1.2351x over previous
#include <cuda_runtime.h>
#include <cuda_bf16.h>
#include <math.h>

#define NN 50000
#define EE 800000
#define GG 512
#define LN_EPS 1e-5f
#define NEG_SLOPE 0.2f

// ---------------- device scratch ----------------
__device__ float g_xl[NN * 256];
__device__ float g_xr[NN * 256];
__device__ float g_h[NN * 256];
__device__ float g_acc[NN * 256];
__device__ int   g_rowptr[NN + 1];
__device__ int   g_cnt[NN];
__device__ int   g_eidx[EE];
__device__ float g_red[2];
__device__ float g_pool[GG * 64];
__device__ float g_pcnt[GG];

__device__ __forceinline__ float lrelu(float v) {
    return v > 0.f ? v : NEG_SLOPE * v;
}

// ---------------- CSR build ----------------
__global__ void k_zero_cnt() {
    int i = blockIdx.x * blockDim.x + threadIdx.x;
    if (i < NN) g_cnt[i] = 0;
}

__global__ void k_hist(const int* __restrict__ dst) {
    int e = blockIdx.x * blockDim.x + threadIdx.x;
    if (e < EE) atomicAdd(&g_cnt[dst[e]], 1);
}

__global__ void k_scan() {
    __shared__ int sh[1024];
    __shared__ int s_carry;
    int tid = threadIdx.x;
    if (tid == 0) { s_carry = 0; g_rowptr[0] = 0; }
    __syncthreads();
    for (int base = 0; base < NN; base += 1024) {
        int i = base + tid;
        int v = (i < NN) ? g_cnt[i] : 0;
        sh[tid] = v;
        __syncthreads();
        #pragma unroll
        for (int off = 1; off < 1024; off <<= 1) {
            int t = (tid >= off) ? sh[tid - off] : 0;
            __syncthreads();
            sh[tid] += t;
            __syncthreads();
        }
        int inc = sh[tid];
        int carry = s_carry;
        if (i < NN) {
            g_rowptr[i + 1] = carry + inc;
            g_cnt[i] = carry + inc - v;
        }
        __syncthreads();
        if (tid == 1023) s_carry = carry + sh[1023];
        __syncthreads();
    }
}

__global__ void k_scatter(const int* __restrict__ dst) {
    int e = blockIdx.x * blockDim.x + threadIdx.x;
    if (e < EE) {
        int pos = atomicAdd(&g_cnt[dst[e]], 1);
        g_eidx[pos] = e;
    }
}

// ---------------- fused dual GEMM: Yl = X@Wl+bl, Yr = X@Wr+br ----------------
// tile 128(M) x 64(N) x 16(K); 256 threads; 8x4 micro-tile per thread per output.
__global__ __launch_bounds__(256) void k_gemm_dual(
    const float* __restrict__ X,
    const float* __restrict__ Wl, const float* __restrict__ bl,
    const float* __restrict__ Wr, const float* __restrict__ br,
    float* __restrict__ Yl, float* __restrict__ Yr,
    int rows, int K, int M)
{
    __shared__ float As[16][132];
    __shared__ float Bls[16][64];
    __shared__ float Brs[16][64];

    int block_row = blockIdx.y * 128;
    int block_col = blockIdx.x * 64;
    int t = threadIdx.x;
    int tx = t & 15;   // 16 col-groups of 4
    int ty = t >> 4;   // 16 row-groups of 8

    float accl[8][4], accr[8][4];
    #pragma unroll
    for (int i = 0; i < 8; i++)
        #pragma unroll
        for (int j = 0; j < 4; j++) { accl[i][j] = 0.f; accr[i][j] = 0.f; }

    for (int k0 = 0; k0 < K; k0 += 16) {
        // A tile: 128 rows x 16 k, loaded as float4 along k, stored transposed
        #pragma unroll
        for (int c = 0; c < 2; c++) {
            int id = t + c * 256;
            int r = id >> 2;
            int kc = id & 3;
            int grow = block_row + r;
            float4 v = make_float4(0.f, 0.f, 0.f, 0.f);
            if (grow < rows)
                v = *(const float4*)&X[(size_t)grow * K + k0 + kc * 4];
            As[kc * 4 + 0][r] = v.x;
            As[kc * 4 + 1][r] = v.y;
            As[kc * 4 + 2][r] = v.z;
            As[kc * 4 + 3][r] = v.w;
        }
        // B tiles: 16 k x 64 n each
        {
            int k = t >> 4;
            int nc = t & 15;
            const float* pl = &Wl[(size_t)(k0 + k) * M + block_col + nc * 4];
            const float* pr = &Wr[(size_t)(k0 + k) * M + block_col + nc * 4];
            float4 vl = *(const float4*)pl;
            float4 vr = *(const float4*)pr;
            Bls[k][nc * 4 + 0] = vl.x; Bls[k][nc * 4 + 1] = vl.y;
            Bls[k][nc * 4 + 2] = vl.z; Bls[k][nc * 4 + 3] = vl.w;
            Brs[k][nc * 4 + 0] = vr.x; Brs[k][nc * 4 + 1] = vr.y;
            Brs[k][nc * 4 + 2] = vr.z; Brs[k][nc * 4 + 3] = vr.w;
        }
        __syncthreads();
        #pragma unroll
        for (int k = 0; k < 16; k++) {
            float a[8];
            #pragma unroll
            for (int i = 0; i < 8; i++) a[i] = As[k][ty * 8 + i];
            float blv[4], brv[4];
            #pragma unroll
            for (int j = 0; j < 4; j++) { blv[j] = Bls[k][tx * 4 + j]; brv[j] = Brs[k][tx * 4 + j]; }
            #pragma unroll
            for (int i = 0; i < 8; i++)
                #pragma unroll
                for (int j = 0; j < 4; j++) {
                    accl[i][j] += a[i] * blv[j];
                    accr[i][j] += a[i] * brv[j];
                }
        }
        __syncthreads();
    }

    #pragma unroll
    for (int i = 0; i < 8; i++) {
        int r = block_row + ty * 8 + i;
        if (r < rows) {
            #pragma unroll
            for (int j = 0; j < 4; j++) {
                int c = block_col + tx * 4 + j;
                Yl[(size_t)r * M + c] = accl[i][j] + bl[c];
                Yr[(size_t)r * M + c] = accr[i][j] + br[c];
            }
        }
    }
}

// ---------------- single-pass edge attention (online softmax) ----------------
// one warp per destination node, running-max rescaled accumulation.
template <int H>
__global__ __launch_bounds__(256) void k_edge_attn(
    const int* __restrict__ srcArr,
    const float* __restrict__ att,
    const float* __restrict__ bias)
{
    const int DM = H * 64;
    int warp = (blockIdx.x * blockDim.x + threadIdx.x) >> 5;
    int lane = threadIdx.x & 31;
    if (warp >= NN) return;
    int dn = warp;

    float xr0[H], xr1[H], at0[H], at1[H];
    #pragma unroll
    for (int h = 0; h < H; h++) {
        xr0[h] = g_xr[(size_t)dn * DM + h * 64 + lane];
        xr1[h] = g_xr[(size_t)dn * DM + h * 64 + lane + 32];
        at0[h] = att[h * 64 + lane];
        at1[h] = att[h * 64 + lane + 32];
    }

    int start = g_rowptr[dn];
    int end   = g_rowptr[dn + 1];

    float m[H], den[H], acc0[H], acc1[H];
    #pragma unroll
    for (int h = 0; h < H; h++) {
        m[h] = -INFINITY; den[h] = 0.f; acc0[h] = 0.f; acc1[h] = 0.f;
    }

    for (int j = start; j < end; j++) {
        int e = g_eidx[j];
        int s = srcArr[e];
        const float* xlrow = &g_xl[(size_t)s * DM];
        #pragma unroll
        for (int h = 0; h < H; h++) {
            float xl0 = xlrow[h * 64 + lane];
            float xl1 = xlrow[h * 64 + lane + 32];
            float p = lrelu(xl0 + xr0[h]) * at0[h] + lrelu(xl1 + xr1[h]) * at1[h];
            #pragma unroll
            for (int off = 16; off > 0; off >>= 1)
                p += __shfl_xor_sync(0xffffffffu, p, off);
            // online softmax update (p is warp-uniform)
            if (p > m[h]) {
                float sc = __expf(m[h] - p);   // exp(-inf) = 0 on first edge
                den[h] *= sc; acc0[h] *= sc; acc1[h] *= sc;
                m[h] = p;
            }
            float w = __expf(p - m[h]);
            den[h] += w;
            acc0[h] += w * xl0;
            acc1[h] += w * xl1;
        }
    }

    #pragma unroll
    for (int h = 0; h < H; h++) {
        float inv = (den[h] > 0.f) ? (1.f / den[h]) : 0.f;
        g_acc[(size_t)dn * DM + h * 64 + lane]      = acc0[h] * inv + bias[h * 64 + lane];
        g_acc[(size_t)dn * DM + h * 64 + lane + 32] = acc1[h] * inv + bias[h * 64 + lane + 32];
    }
}

// ---------------- graph layernorm ----------------
__global__ void k_zero_red() {
    if (threadIdx.x < 2 && blockIdx.x == 0) g_red[threadIdx.x] = 0.f;
}

__global__ __launch_bounds__(256) void k_ln_reduce(int count) {
    float s = 0.f, s2 = 0.f;
    for (int i = blockIdx.x * blockDim.x + threadIdx.x; i < count;
         i += gridDim.x * blockDim.x) {
        float v = g_acc[i];
        s += v; s2 += v * v;
    }
    #pragma unroll
    for (int off = 16; off > 0; off >>= 1) {
        s  += __shfl_xor_sync(0xffffffffu, s,  off);
        s2 += __shfl_xor_sync(0xffffffffu, s2, off);
    }
    __shared__ float shs[8], shs2[8];
    int w = threadIdx.x >> 5, l = threadIdx.x & 31;
    if (l == 0) { shs[w] = s; shs2[w] = s2; }
    __syncthreads();
    if (threadIdx.x == 0) {
        float a = 0.f, b = 0.f;
        for (int i = 0; i < (int)(blockDim.x >> 5); i++) { a += shs[i]; b += shs2[i]; }
        atomicAdd(&g_red[0], a);
        atomicAdd(&g_red[1], b);
    }
}

__global__ __launch_bounds__(256) void k_ln_apply(
    const float* __restrict__ gamma, const float* __restrict__ beta,
    int count, int DM, float invCount, int residual)
{
    int i = blockIdx.x * blockDim.x + threadIdx.x;
    if (i >= count) return;
    int c = i % DM;
    float mu  = g_red[0] * invCount;
    float var = g_red[1] * invCount - mu * mu;
    float rs  = rsqrtf(var + LN_EPS);
    float v = (g_acc[i] - mu) * rs * gamma[c] + beta[c];
    v = fmaxf(v, 0.f);
    if (residual) v += g_h[i];
    g_h[i] = v;
}

// ---------------- pooling + MLP head ----------------
__global__ void k_zero_pool() {
    int i = blockIdx.x * blockDim.x + threadIdx.x;
    if (i < GG * 64) g_pool[i] = 0.f;
    if (i < GG) g_pcnt[i] = 0.f;
}

__global__ __launch_bounds__(256) void k_pool(const int* __restrict__ batch) {
    int idx = blockIdx.x * blockDim.x + threadIdx.x;
    if (idx >= NN * 64) return;
    int node = idx >> 6;
    int c = idx & 63;
    int g = batch[node];
    atomicAdd(&g_pool[g * 64 + c], g_h[idx]);
    if (c == 0) atomicAdd(&g_pcnt[g], 1.f);
}

__global__ __launch_bounds__(64) void k_mlp(
    const float* __restrict__ Wh1, const float* __restrict__ bh1,
    const float* __restrict__ Wh2, const float* __restrict__ bh2,
    float* __restrict__ out)
{
    int g = blockIdx.x;
    int j = threadIdx.x;
    __shared__ float z[64];
    __shared__ float red[64];
    float cnt = fmaxf(g_pcnt[g], 1.f);
    z[j] = g_pool[g * 64 + j] / cnt;
    __syncthreads();
    float hv = bh1[j];
    #pragma unroll 8
    for (int k = 0; k < 64; k++) hv += z[k] * Wh1[k * 64 + j];
    hv = fmaxf(hv, 0.f);
    red[j] = hv * Wh2[j];
    __syncthreads();
    for (int off = 32; off > 0; off >>= 1) {
        if (j < off) red[j] += red[j + off];
        __syncthreads();
    }
    if (j == 0) out[g] = red[0] + bh2[0];
}

// ---------------- host orchestration ----------------
extern "C" void kernel_launch(void* const* d_in, const int* in_sizes, int n_in,
                              void* d_out, int out_size)
{
    const float* x     = (const float*)d_in[0];
    const int*   ei    = (const int*)d_in[1];
    const int*   srcA  = ei;
    const int*   dstA  = ei + EE;
    const int*   batch = (const int*)d_in[2];

    const float* Wl[3];  const float* bl[3];
    const float* Wr[3];  const float* br[3];
    const float* att[3]; const float* bias[3];
    const float* lng[3]; const float* lnb[3];
    for (int l = 0; l < 3; l++) {
        int base = 3 + 8 * l;
        Wl[l]   = (const float*)d_in[base + 0];
        bl[l]   = (const float*)d_in[base + 1];
        Wr[l]   = (const float*)d_in[base + 2];
        br[l]   = (const float*)d_in[base + 3];
        att[l]  = (const float*)d_in[base + 4];
        bias[l] = (const float*)d_in[base + 5];
        lng[l]  = (const float*)d_in[base + 6];
        lnb[l]  = (const float*)d_in[base + 7];
    }
    const float* Wh1 = (const float*)d_in[27];
    const float* bh1 = (const float*)d_in[28];
    const float* Wh2 = (const float*)d_in[29];
    const float* bh2 = (const float*)d_in[30];
    float* out = (float*)d_out;

    float *p_xl, *p_xr, *p_h;
    cudaGetSymbolAddress((void**)&p_xl, g_xl);
    cudaGetSymbolAddress((void**)&p_xr, g_xr);
    cudaGetSymbolAddress((void**)&p_h,  g_h);

    // CSR build
    k_zero_cnt<<<(NN + 255) / 256, 256>>>();
    k_hist<<<(EE + 255) / 256, 256>>>(dstA);
    k_scan<<<1, 1024>>>();
    k_scatter<<<(EE + 255) / 256, 256>>>(dstA);

    const int din_[3]  = {128, 256, 64};
    const int dm_[3]   = {256, 64, 64};
    const int res_[3]  = {0, 0, 1};

    for (int l = 0; l < 3; l++) {
        const float* Xin = (l == 0) ? x : p_h;
        int din = din_[l], dm = dm_[l];
        dim3 ggrid(dm / 64, (NN + 127) / 128);
        k_gemm_dual<<<ggrid, 256>>>(Xin, Wl[l], bl[l], Wr[l], br[l],
                                    p_xl, p_xr, NN, din, dm);

        int edge_blocks = (NN * 32 + 255) / 256;
        if (l == 0) k_edge_attn<4><<<edge_blocks, 256>>>(srcA, att[l], bias[l]);
        else        k_edge_attn<1><<<edge_blocks, 256>>>(srcA, att[l], bias[l]);

        int count = NN * dm;
        k_zero_red<<<1, 32>>>();
        int rgrid = (count + 255) / 256;
        if (rgrid > 2048) rgrid = 2048;
        k_ln_reduce<<<rgrid, 256>>>(count);
        k_ln_apply<<<(count + 255) / 256, 256>>>(lng[l], lnb[l], count, dm,
                                                 1.f / (float)count, res_[l]);
    }

    k_zero_pool<<<(GG * 64 + 255) / 256, 256>>>();
    k_pool<<<(NN * 64 + 255) / 256, 256>>>(batch);
    k_mlp<<<GG, 64>>>(Wh1, bh1, Wh2, bh2, out);

    (void)in_sizes; (void)n_in; (void)out_size;
}